// round 1
// baseline (speedup 1.0000x reference)
#include <cuda_runtime.h>

// Problem constants (N=8192, X=H=Y=1024), all fixed by the reference.
#define NROWS   8192
#define XDIM    1024
#define CHUNKS  64
#define RPC     128   // rows per scan chunk (64*128 = 8192)

// Scratch (allocation-free rule: __device__ globals)
__device__ float g_Xs[(size_t)NROWS * XDIM];   // exclusive row-prefix-sum of x
__device__ float g_P [(size_t)NROWS * XDIM];   // P = Xs @ M^T
__device__ float g_M [(size_t)XDIM * XDIM];    // M = Wq^T Wk
__device__ float g_part[CHUNKS * XDIM];
__device__ float g_off [CHUNKS * XDIM];
__device__ float g_u[XDIM];
__device__ float g_w[XDIM];
__device__ float g_c0;

// ---------------------------------------------------------------------------
// Scan kernels: exclusive prefix sum of x along rows (per column)
// ---------------------------------------------------------------------------
__global__ void colsum_kernel(const float* __restrict__ x) {
    int col = blockIdx.x * 256 + threadIdx.x;
    int ch  = blockIdx.y;
    const float* p = x + (size_t)ch * RPC * XDIM + col;
    float s = 0.f;
    #pragma unroll 8
    for (int r = 0; r < RPC; r++) s += p[(size_t)r * XDIM];
    g_part[ch * XDIM + col] = s;
}

__global__ void scanoff_kernel() {
    int col = blockIdx.x * 256 + threadIdx.x;
    float run = 0.f;
    #pragma unroll
    for (int c = 0; c < CHUNKS; c++) {
        g_off[c * XDIM + col] = run;
        run += g_part[c * XDIM + col];
    }
}

__global__ void writeXs_kernel(const float* __restrict__ x) {
    int col = blockIdx.x * 256 + threadIdx.x;
    int ch  = blockIdx.y;
    float run = g_off[ch * XDIM + col];
    size_t base = (size_t)ch * RPC * XDIM + col;
    #pragma unroll 4
    for (int r = 0; r < RPC; r++) {
        size_t idx = base + (size_t)r * XDIM;
        g_Xs[idx] = run;
        run += x[idx];
    }
}

// ---------------------------------------------------------------------------
// Small vectors: u = Wq^T bk, w = Wk^T bq, c0 = bq . bk
// ---------------------------------------------------------------------------
__global__ void smallvec_kernel(const float* __restrict__ Wq,
                                const float* __restrict__ Wk,
                                const float* __restrict__ bk,
                                const float* __restrict__ bq) {
    int a = blockIdx.x * 256 + threadIdx.x;
    float su = 0.f, sw = 0.f;
    for (int h = 0; h < XDIM; h++) {
        float bkh = bk[h], bqh = bq[h];
        su += Wq[(size_t)h * XDIM + a] * bkh;
        sw += Wk[(size_t)h * XDIM + a] * bqh;
    }
    g_u[a] = su;
    g_w[a] = sw;
}

__global__ void c0_kernel(const float* __restrict__ bq, const float* __restrict__ bk) {
    __shared__ float red[256];
    float s = 0.f;
    for (int i = threadIdx.x; i < XDIM; i += 256) s += bq[i] * bk[i];
    red[threadIdx.x] = s;
    __syncthreads();
    for (int st = 128; st > 0; st >>= 1) {
        if (threadIdx.x < st) red[threadIdx.x] += red[threadIdx.x + st];
        __syncthreads();
    }
    if (threadIdx.x == 0) g_c0 = red[0];
}

// ---------------------------------------------------------------------------
// Generic strided fp32 GEMM: C[m][n] = sum_k A[m*sam + k*sak] * B[n*sbn + k*sbk]
// Tiles 128x128x16, 256 threads, 8x8 per-thread micro-tile (4+4 split for
// conflict-free float4 LDS). All dims assumed multiples of 128/16.
// ---------------------------------------------------------------------------
#define BM 128
#define BN 128
#define BKT 16

__global__ void __launch_bounds__(256)
gemm128_kernel(const float* __restrict__ A, int sam, int sak,
               const float* __restrict__ B, int sbn, int sbk,
               float* __restrict__ C, int N, int K) {
    __shared__ float As[BKT][BM];
    __shared__ float Bs[BKT][BN];

    const int tid = threadIdx.x;
    const int m0 = blockIdx.y * BM;
    const int n0 = blockIdx.x * BN;
    const int tx = tid & 15;
    const int ty = tid >> 4;

    const int lm  = tid & 127;        // load row (A) / load col (B)
    const int lk0 = (tid >> 7) * 8;   // 0 or 8

    float acc[8][8];
    #pragma unroll
    for (int i = 0; i < 8; i++)
        #pragma unroll
        for (int j = 0; j < 8; j++) acc[i][j] = 0.f;

    const float* pa = A + (size_t)(m0 + lm) * sam + (size_t)lk0 * sak;
    const float* pb = B + (size_t)(n0 + lm) * sbn + (size_t)lk0 * sbk;

    for (int k0 = 0; k0 < K; k0 += BKT) {
        #pragma unroll
        for (int j = 0; j < 8; j++) As[lk0 + j][lm] = pa[(size_t)j * sak];
        #pragma unroll
        for (int j = 0; j < 8; j++) Bs[lk0 + j][lm] = pb[(size_t)j * sbk];
        pa += (size_t)BKT * sak;
        pb += (size_t)BKT * sbk;
        __syncthreads();

        #pragma unroll
        for (int kk = 0; kk < BKT; kk++) {
            float4 a0 = *(const float4*)&As[kk][ty * 4];
            float4 a1 = *(const float4*)&As[kk][64 + ty * 4];
            float4 b0 = *(const float4*)&Bs[kk][tx * 4];
            float4 b1 = *(const float4*)&Bs[kk][64 + tx * 4];
            float av[8] = {a0.x, a0.y, a0.z, a0.w, a1.x, a1.y, a1.z, a1.w};
            float bv[8] = {b0.x, b0.y, b0.z, b0.w, b1.x, b1.y, b1.z, b1.w};
            #pragma unroll
            for (int i = 0; i < 8; i++)
                #pragma unroll
                for (int j = 0; j < 8; j++) acc[i][j] += av[i] * bv[j];
        }
        __syncthreads();
    }

    // Epilogue: rows {ty*4..+3, 64+ty*4..+3}, cols {tx*4..+3, 64+tx*4..+3}
    #pragma unroll
    for (int i = 0; i < 8; i++) {
        int m = m0 + ((i < 4) ? (ty * 4 + i) : (64 + ty * 4 + i - 4));
        float4 c0v = make_float4(acc[i][0], acc[i][1], acc[i][2], acc[i][3]);
        float4 c1v = make_float4(acc[i][4], acc[i][5], acc[i][6], acc[i][7]);
        *(float4*)&C[(size_t)m * N + n0 + tx * 4]      = c0v;
        *(float4*)&C[(size_t)m * N + n0 + 64 + tx * 4] = c1v;
    }
}

// ---------------------------------------------------------------------------
// Finalize: r_i = x_i . P_i + i*(u . x_i) + w . Xs_i + i*c0; out[i,:] = r_i
// ---------------------------------------------------------------------------
__global__ void finalize_kernel(const float* __restrict__ x,
                                float* __restrict__ out) {
    const int i = blockIdx.x;
    const float fi = (float)i;
    const int tid = threadIdx.x;

    float p = 0.f;
    size_t rb = (size_t)i * XDIM;
    #pragma unroll
    for (int c = tid; c < XDIM; c += 256) {
        float xv = x[rb + c];
        p += xv * (g_P[rb + c] + fi * g_u[c]) + g_w[c] * g_Xs[rb + c];
    }

    __shared__ float red[256];
    red[tid] = p;
    __syncthreads();
    for (int st = 128; st > 0; st >>= 1) {
        if (tid < st) red[tid] += red[tid + st];
        __syncthreads();
    }
    float r = red[0] + fi * g_c0;

    float4 rv = make_float4(r, r, r, r);
    #pragma unroll
    for (int c = tid * 4; c < XDIM; c += 256 * 4)
        *(float4*)&out[rb + c] = rv;
}

// ---------------------------------------------------------------------------
// kernel_launch
// Inputs (metadata order): x, Wk, bk, Wv, bv, Wq, bq   (Wv, bv unused — the
// reference overwrites V with ones, so out[i,:] = rowsum of masked scores)
// ---------------------------------------------------------------------------
extern "C" void kernel_launch(void* const* d_in, const int* in_sizes, int n_in,
                              void* d_out, int out_size) {
    const float* x  = (const float*)d_in[0];
    const float* Wk = (const float*)d_in[1];
    const float* bk = (const float*)d_in[2];
    const float* Wq = (const float*)d_in[5];
    const float* bq = (const float*)d_in[6];
    float* out = (float*)d_out;

    float* Xs; cudaGetSymbolAddress((void**)&Xs, g_Xs);
    float* P;  cudaGetSymbolAddress((void**)&P,  g_P);
    float* M;  cudaGetSymbolAddress((void**)&M,  g_M);

    // 1) exclusive prefix sum of x -> g_Xs
    colsum_kernel<<<dim3(XDIM / 256, CHUNKS), 256>>>(x);
    scanoff_kernel<<<XDIM / 256, 256>>>();
    writeXs_kernel<<<dim3(XDIM / 256, CHUNKS), 256>>>(x);

    // 2) M = Wq^T Wk  (TN: A[h][a] stride sam=1, sak=XDIM)
    gemm128_kernel<<<dim3(XDIM / BN, XDIM / BM), 256>>>(
        Wq, 1, XDIM, Wk, 1, XDIM, M, XDIM, XDIM);

    // 3) u, w, c0
    smallvec_kernel<<<XDIM / 256, 256>>>(Wq, Wk, bk, bq);
    c0_kernel<<<1, 256>>>(bq, bk);

    // 4) P = Xs @ M^T  (NT: A row-major sam=XDIM, sak=1; B = M sbn=XDIM, sbk=1)
    gemm128_kernel<<<dim3(XDIM / BN, NROWS / BM), 256>>>(
        Xs, XDIM, 1, M, XDIM, 1, P, XDIM, XDIM);

    // 5) fused row-dot + broadcast
    finalize_kernel<<<NROWS, 256>>>(x, out);
}

// round 3
// speedup vs baseline: 3.5160x; 3.5160x over previous
#include <cuda_runtime.h>
#include <cuda_bf16.h>
#include <cstdint>

// Problem constants (N=8192, X=H=Y=1024)
#define NR 8192
#define XD 1024
#define KEXT 3072          // 3x bf16-split extended K
#define CHUNKS 64
#define RPC 128

// ---------------------------------------------------------------------------
// Device scratch (allocation-free rule)
// ---------------------------------------------------------------------------
__device__ float g_Xs[(size_t)NR * XD];            // exclusive prefix-sum of x
__device__ float g_P [(size_t)NR * XD];            // P = Xs @ M^T
__device__ float g_M [(size_t)XD * XD];            // M = Wq^T Wk
__device__ float g_WqT[(size_t)XD * XD];
__device__ float g_WkT[(size_t)XD * XD];
__device__ __nv_bfloat16 g_Xse [(size_t)NR * KEXT];   // ext A-mode of Xs
__device__ __nv_bfloat16 g_Me  [(size_t)XD * KEXT];   // ext B-mode of M
__device__ __nv_bfloat16 g_WqTe[(size_t)XD * KEXT];   // ext A-mode of Wq^T
__device__ __nv_bfloat16 g_WkTe[(size_t)XD * KEXT];   // ext B-mode of Wk^T
__device__ float g_part[CHUNKS * XD];
__device__ float g_off [CHUNKS * XD];
__device__ float g_upart[8 * XD];
__device__ float g_wpart[8 * XD];
__device__ float g_u[XD];
__device__ float g_w[XD];
__device__ float g_c0;

// ---------------------------------------------------------------------------
// PTX helpers (base sm_80+ ISA only — no arch-suffixed instructions!)
// ---------------------------------------------------------------------------
__device__ __forceinline__ uint32_t smem_u32(const void* p) {
    uint32_t a;
    asm("{ .reg .u64 t; cvta.to.shared.u64 t, %1; cvt.u32.u64 %0, t; }" : "=r"(a) : "l"(p));
    return a;
}
#define CP_ASYNC16(dst, src) \
    asm volatile("cp.async.cg.shared.global [%0], [%1], 16;" :: "r"(dst), "l"(src))
#define CP_COMMIT() asm volatile("cp.async.commit_group;" ::: "memory")
#define CP_WAIT1()  asm volatile("cp.async.wait_group 1;" ::: "memory")
#define CP_WAIT0()  asm volatile("cp.async.wait_group 0;" ::: "memory")

__device__ __forceinline__ void ldsm4(uint32_t& r0, uint32_t& r1, uint32_t& r2,
                                      uint32_t& r3, uint32_t addr) {
    asm volatile("ldmatrix.sync.aligned.m8n8.x4.shared.b16 {%0,%1,%2,%3}, [%4];"
                 : "=r"(r0), "=r"(r1), "=r"(r2), "=r"(r3) : "r"(addr));
}
__device__ __forceinline__ void mma_bf16(float* c, uint32_t a0, uint32_t a1,
                                         uint32_t a2, uint32_t a3,
                                         uint32_t b0, uint32_t b1) {
    asm volatile(
        "mma.sync.aligned.m16n8k16.row.col.f32.bf16.bf16.f32 "
        "{%0,%1,%2,%3}, {%4,%5,%6,%7}, {%8,%9}, {%0,%1,%2,%3};"
        : "+f"(c[0]), "+f"(c[1]), "+f"(c[2]), "+f"(c[3])
        : "r"(a0), "r"(a1), "r"(a2), "r"(a3), "r"(b0), "r"(b1));
}
__device__ __forceinline__ uint32_t swz(uint32_t b) { return b ^ ((b >> 3) & 0x70); }

// ---------------------------------------------------------------------------
// bf16x3 GEMM:  C[m][n] = sum_k A[m][k]*B[n][k],  A:[Mrows][KEXT] B:[1024][KEXT]
// 128x128 tile, BK=64 bf16/stage (128B rows, SW128), cp.async double buffer,
// 8 warps: warp_m = wid&3 (32 rows), warp_n = wid>>2 (64 cols).
// ---------------------------------------------------------------------------
#define BKE 64
#define TILEB (128 * BKE * 2)        // 16384 bytes per operand tile
#define STAGEB (2 * TILEB)           // A + B
#define GSMEM (1024 + 2 * STAGEB)    // alignment slack + 2 stages

__global__ void __launch_bounds__(256)
gemm_bf16x3(const __nv_bfloat16* __restrict__ A,
            const __nv_bfloat16* __restrict__ B,
            float* __restrict__ C) {
    extern __shared__ char smem_raw[];
    uint32_t raw = smem_u32(smem_raw);
    uint32_t ab = (raw + 1023u) & ~1023u;   // 1024-aligned

    const int tid = threadIdx.x;
    const int wid = tid >> 5;
    const int lane = tid & 31;
    const int m0 = blockIdx.y * 128;
    const int n0 = blockIdx.x * 128;
    const int wm = (wid & 3) * 32;    // warp row offset
    const int wn = (wid >> 2) * 64;   // warp col offset

    const int NS = KEXT / BKE;        // 48 stages

    // per-thread load coords: 1024 16B-units per tile, 4 per thread per tile
    // unit u: row = u>>3, c16 = u&7
    const __nv_bfloat16* gA = A + (size_t)m0 * KEXT;
    const __nv_bfloat16* gB = B + (size_t)n0 * KEXT;

    float acc[2][8][4];
    #pragma unroll
    for (int i = 0; i < 2; i++)
        #pragma unroll
        for (int j = 0; j < 8; j++)
            #pragma unroll
            for (int q = 0; q < 4; q++) acc[i][j][q] = 0.f;

    auto issue = [&](int kt) {
        const uint32_t sa = ab + (kt & 1) * STAGEB;
        const uint32_t sb = sa + TILEB;
        const int kb = kt * BKE;
        #pragma unroll
        for (int i = 0; i < 4; i++) {
            int u = tid + i * 256;
            int row = u >> 3, c16 = u & 7;
            uint32_t so = swz((uint32_t)(row * 128 + c16 * 16));
            CP_ASYNC16(sa + so, gA + (size_t)row * KEXT + kb + c16 * 8);
            CP_ASYNC16(sb + so, gB + (size_t)row * KEXT + kb + c16 * 8);
        }
        CP_COMMIT();
    };

    issue(0);
    const int lr = lane & 15;   // ldmatrix row within 16
    const int lc = lane >> 4;   // ldmatrix 16B chunk

    for (int kt = 0; kt < NS; kt++) {
        const uint32_t sa = ab + (kt & 1) * STAGEB;
        const uint32_t sb = sa + TILEB;
        if (kt + 1 < NS) { issue(kt + 1); CP_WAIT1(); }
        else             { CP_WAIT0(); }
        __syncthreads();

        #pragma unroll
        for (int s = 0; s < BKE / 16; s++) {          // 4 k16 steps
            const int xcol = s * 32 + lc * 16;        // byte col in 128B row
            uint32_t a[2][4];
            #pragma unroll
            for (int mm = 0; mm < 2; mm++) {
                int row = wm + mm * 16 + lr;
                uint32_t addr = sa + row * 128 + (xcol ^ ((row & 7) * 16));
                ldsm4(a[mm][0], a[mm][1], a[mm][2], a[mm][3], addr);
            }
            #pragma unroll
            for (int nb = 0; nb < 4; nb++) {          // 4 n16 groups = 8 n8
                int row = wn + nb * 16 + lr;
                uint32_t addr = sb + row * 128 + (xcol ^ ((row & 7) * 16));
                uint32_t r0, r1, r2, r3;
                ldsm4(r0, r1, r2, r3, addr);
                #pragma unroll
                for (int mm = 0; mm < 2; mm++) {
                    mma_bf16(acc[mm][2 * nb],     a[mm][0], a[mm][1], a[mm][2], a[mm][3], r0, r2);
                    mma_bf16(acc[mm][2 * nb + 1], a[mm][0], a[mm][1], a[mm][2], a[mm][3], r1, r3);
                }
            }
        }
        __syncthreads();
    }

    // Epilogue: fp32 accum -> C
    const int qr = lane >> 2;          // row in m8
    const int qc = (lane & 3) * 2;     // col pair
    #pragma unroll
    for (int mm = 0; mm < 2; mm++) {
        #pragma unroll
        for (int j = 0; j < 8; j++) {
            int r = m0 + wm + mm * 16 + qr;
            int c = n0 + wn + j * 8 + qc;
            *(float2*)&C[(size_t)r * XD + c]       = make_float2(acc[mm][j][0], acc[mm][j][1]);
            *(float2*)&C[(size_t)(r + 8) * XD + c] = make_float2(acc[mm][j][2], acc[mm][j][3]);
        }
    }
}

// ---------------------------------------------------------------------------
// fp32 -> bf16x3 extended operand. modeA: [hi | lo | hi]; else B: [hi | hi | lo]
// ---------------------------------------------------------------------------
__global__ void ext_convert(const float* __restrict__ in,
                            __nv_bfloat16* __restrict__ out, int modeA) {
    const int row = blockIdx.x;
    const int c = threadIdx.x * 4;
    float4 v = *(const float4*)(in + (size_t)row * XD + c);
    float vv[4] = {v.x, v.y, v.z, v.w};
    unsigned short hb[4], lb[4];
    #pragma unroll
    for (int i = 0; i < 4; i++) {
        __nv_bfloat16 h = __float2bfloat16_rn(vv[i]);
        __nv_bfloat16 l = __float2bfloat16_rn(vv[i] - __bfloat162float(h));
        hb[i] = *reinterpret_cast<unsigned short*>(&h);
        lb[i] = *reinterpret_cast<unsigned short*>(&l);
    }
    ushort4 hv = make_ushort4(hb[0], hb[1], hb[2], hb[3]);
    ushort4 lv = make_ushort4(lb[0], lb[1], lb[2], lb[3]);
    unsigned short* ob = reinterpret_cast<unsigned short*>(out) + (size_t)row * KEXT;
    *(ushort4*)(ob + c) = hv;
    if (modeA) {
        *(ushort4*)(ob + XD + c)     = lv;
        *(ushort4*)(ob + 2 * XD + c) = hv;
    } else {
        *(ushort4*)(ob + XD + c)     = hv;
        *(ushort4*)(ob + 2 * XD + c) = lv;
    }
}

// ---------------------------------------------------------------------------
// Transpose 1024x1024
// ---------------------------------------------------------------------------
__global__ void transpose_kernel(const float* __restrict__ in, float* __restrict__ out) {
    __shared__ float t[32][33];
    int bx = blockIdx.x * 32, by = blockIdx.y * 32;
    #pragma unroll
    for (int j = 0; j < 32; j += 8)
        t[threadIdx.y + j][threadIdx.x] = in[(size_t)(by + threadIdx.y + j) * XD + bx + threadIdx.x];
    __syncthreads();
    #pragma unroll
    for (int j = 0; j < 32; j += 8)
        out[(size_t)(bx + threadIdx.y + j) * XD + by + threadIdx.x] = t[threadIdx.x][threadIdx.y + j];
}

// ---------------------------------------------------------------------------
// Scan kernels (exclusive prefix sum of x rows)
// ---------------------------------------------------------------------------
__global__ void colsum_kernel(const float* __restrict__ x) {
    int col = blockIdx.x * 256 + threadIdx.x;
    int ch  = blockIdx.y;
    const float* p = x + (size_t)ch * RPC * XD + col;
    float s = 0.f;
    #pragma unroll 8
    for (int r = 0; r < RPC; r++) s += p[(size_t)r * XD];
    g_part[ch * XD + col] = s;
}
__global__ void scanoff_kernel() {
    int col = blockIdx.x * 256 + threadIdx.x;
    float run = 0.f;
    #pragma unroll
    for (int c = 0; c < CHUNKS; c++) {
        g_off[c * XD + col] = run;
        run += g_part[c * XD + col];
    }
}
__global__ void writeXs_kernel(const float* __restrict__ x) {
    int col = blockIdx.x * 256 + threadIdx.x;
    int ch  = blockIdx.y;
    float run = g_off[ch * XD + col];
    size_t base = (size_t)ch * RPC * XD + col;
    #pragma unroll 4
    for (int r = 0; r < RPC; r++) {
        size_t idx = base + (size_t)r * XD;
        g_Xs[idx] = run;
        run += x[idx];
    }
}

// ---------------------------------------------------------------------------
// Small vectors: u = Wq^T bk, w = Wk^T bq, c0 = bq.bk
// ---------------------------------------------------------------------------
__global__ void smallvec_part_kernel(const float* __restrict__ Wq,
                                     const float* __restrict__ Wk,
                                     const float* __restrict__ bk,
                                     const float* __restrict__ bq) {
    int a  = blockIdx.x * 256 + threadIdx.x;
    int hb = blockIdx.y;
    float su = 0.f, sw = 0.f;
    #pragma unroll 4
    for (int h = hb * 128; h < hb * 128 + 128; h++) {
        su += Wq[(size_t)h * XD + a] * bk[h];
        sw += Wk[(size_t)h * XD + a] * bq[h];
    }
    g_upart[hb * XD + a] = su;
    g_wpart[hb * XD + a] = sw;
}
__global__ void smallvec_reduce_kernel() {
    int a = blockIdx.x * 256 + threadIdx.x;
    float su = 0.f, sw = 0.f;
    #pragma unroll
    for (int p = 0; p < 8; p++) { su += g_upart[p * XD + a]; sw += g_wpart[p * XD + a]; }
    g_u[a] = su;
    g_w[a] = sw;
}
__global__ void c0_kernel(const float* __restrict__ bq, const float* __restrict__ bk) {
    __shared__ float red[256];
    float s = 0.f;
    for (int i = threadIdx.x; i < XD; i += 256) s += bq[i] * bk[i];
    red[threadIdx.x] = s;
    __syncthreads();
    for (int st = 128; st > 0; st >>= 1) {
        if (threadIdx.x < st) red[threadIdx.x] += red[threadIdx.x + st];
        __syncthreads();
    }
    if (threadIdx.x == 0) g_c0 = red[0];
}

// ---------------------------------------------------------------------------
// Finalize: r_i = x_i.P_i + i*(u.x_i) + w.Xs_i + i*c0 ; out[i,:] = r_i
// ---------------------------------------------------------------------------
__global__ void finalize_kernel(const float* __restrict__ x, float* __restrict__ out) {
    const int i = blockIdx.x;
    const float fi = (float)i;
    const int tid = threadIdx.x;
    float p = 0.f;
    size_t rb = (size_t)i * XD;
    #pragma unroll
    for (int c = tid; c < XD; c += 256) {
        float xv = x[rb + c];
        p += xv * (g_P[rb + c] + fi * g_u[c]) + g_w[c] * g_Xs[rb + c];
    }
    __shared__ float red[256];
    red[tid] = p;
    __syncthreads();
    for (int st = 128; st > 0; st >>= 1) {
        if (tid < st) red[tid] += red[tid + st];
        __syncthreads();
    }
    float r = red[0] + fi * g_c0;
    float4 rv = make_float4(r, r, r, r);
    #pragma unroll
    for (int c = tid * 4; c < XD; c += 256 * 4)
        *(float4*)&out[rb + c] = rv;
}

// ---------------------------------------------------------------------------
// kernel_launch — inputs: x, Wk, bk, Wv, bv, Wq, bq  (Wv/bv unused: V:=ones)
// ---------------------------------------------------------------------------
extern "C" void kernel_launch(void* const* d_in, const int* in_sizes, int n_in,
                              void* d_out, int out_size) {
    const float* x  = (const float*)d_in[0];
    const float* Wk = (const float*)d_in[1];
    const float* bk = (const float*)d_in[2];
    const float* Wq = (const float*)d_in[5];
    const float* bq = (const float*)d_in[6];
    float* out = (float*)d_out;

    float *Xs, *P, *M, *WqT, *WkT;
    __nv_bfloat16 *Xse, *Me, *WqTe, *WkTe;
    cudaGetSymbolAddress((void**)&Xs,   g_Xs);
    cudaGetSymbolAddress((void**)&P,    g_P);
    cudaGetSymbolAddress((void**)&M,    g_M);
    cudaGetSymbolAddress((void**)&WqT,  g_WqT);
    cudaGetSymbolAddress((void**)&WkT,  g_WkT);
    cudaGetSymbolAddress((void**)&Xse,  g_Xse);
    cudaGetSymbolAddress((void**)&Me,   g_Me);
    cudaGetSymbolAddress((void**)&WqTe, g_WqTe);
    cudaGetSymbolAddress((void**)&WkTe, g_WkTe);

    cudaFuncSetAttribute(gemm_bf16x3, cudaFuncAttributeMaxDynamicSharedMemorySize, GSMEM);

    // 1) transposes + ext conversions of the weight operands
    transpose_kernel<<<dim3(32, 32), dim3(32, 8)>>>(Wq, WqT);
    transpose_kernel<<<dim3(32, 32), dim3(32, 8)>>>(Wk, WkT);
    ext_convert<<<XD, 256>>>(WqT, WqTe, 1);   // A-mode
    ext_convert<<<XD, 256>>>(WkT, WkTe, 0);   // B-mode

    // 2) exclusive prefix sum of x -> g_Xs, then ext A-mode
    colsum_kernel<<<dim3(XD / 256, CHUNKS), 256>>>(x);
    scanoff_kernel<<<XD / 256, 256>>>();
    writeXs_kernel<<<dim3(XD / 256, CHUNKS), 256>>>(x);
    ext_convert<<<NR, 256>>>(Xs, Xse, 1);     // A-mode

    // 3) M[a][b] = sum_h WqT[a][h] * WkT[b][h]   (bf16x3 tensor GEMM)
    gemm_bf16x3<<<dim3(XD / 128, XD / 128), 256, GSMEM>>>(WqTe, WkTe, M);
    ext_convert<<<XD, 256>>>(M, Me, 0);       // B-mode

    // 4) u, w, c0
    smallvec_part_kernel<<<dim3(XD / 256, 8), 256>>>(Wq, Wk, bk, bq);
    smallvec_reduce_kernel<<<XD / 256, 256>>>();
    c0_kernel<<<1, 256>>>(bq, bk);

    // 5) P[i][a] = sum_b Xs[i][b] * M[a][b]
    gemm_bf16x3<<<dim3(XD / 128, NR / 128), 256, GSMEM>>>(Xse, Me, P);

    // 6) fused row-dot + broadcast
    finalize_kernel<<<NR, 256>>>(x, out);
}